// round 3
// baseline (speedup 1.0000x reference)
#include <cuda_runtime.h>
#include <math_constants.h>

// Problem constants
#define NND   50000
#define EED   800000
#define DDIM  128
#define HH    8
#define CCH   16
#define LLAY  4
#define QKVS  512   // 4*128 packed output columns: [q|k|v|skip]

// ---------------- scratch (device globals; no allocation allowed) ----------
__device__ __align__(16) float g_x[NND * DDIM];          // node features between layers
__device__ __align__(16) float g_qkvs[NND * QKVS];       // [q|k|v|skip] per node
__device__ __align__(16) float g_sp[EED * HH];           // per-edge raw scores (CSR order)
__device__ __align__(16) float g_Wp[LLAY * DDIM * QKVS]; // packed weights
__device__ __align__(16) float g_bp[LLAY * QKVS];        // packed biases
// CSR build
__device__ int g_deg[NND];
__device__ int g_off[NND + 1];
__device__ int g_cur[NND];
__device__ int g_part[256];
__device__ int g_csr_src[EED];

// ---------------- weight packing -------------------------------------------
__global__ void pack_w(const float* __restrict__ Wq, const float* __restrict__ Wk,
                       const float* __restrict__ Wv, const float* __restrict__ Ws,
                       const float* __restrict__ bq, const float* __restrict__ bk,
                       const float* __restrict__ bv, const float* __restrict__ bs) {
    int i = blockIdx.x * blockDim.x + threadIdx.x;
    if (i < LLAY * DDIM * QKVS) {
        int l = i >> 16;          // 128*512 = 65536
        int k = (i >> 9) & 127;
        int j = i & 511;
        int which = j >> 7, jj = j & 127;
        const float* W = (which == 0) ? Wq : (which == 1) ? Wk : (which == 2) ? Wv : Ws;
        g_Wp[i] = W[l * (DDIM * DDIM) + k * DDIM + jj];
    }
    if (i < LLAY * QKVS) {
        int l = i >> 9, j = i & 511;
        int which = j >> 7, jj = j & 127;
        const float* b = (which == 0) ? bq : (which == 1) ? bk : (which == 2) ? bv : bs;
        g_bp[i] = b[l * DDIM + jj];
    }
}

// ---------------- CSR build --------------------------------------------------
__global__ void deg_zero_k() {
    int i = blockIdx.x * blockDim.x + threadIdx.x;
    if (i < NND) g_deg[i] = 0;
}

__global__ void hist_k(const int* __restrict__ ei) {
    int e = blockIdx.x * blockDim.x + threadIdx.x;
    if (e < EED) atomicAdd(&g_deg[ei[EED + e]], 1);
}

// pass 1: per-block exclusive scan of degrees (256 per block) + per-block totals
__global__ void scan1_k() {
    __shared__ int s[256];
    int t = threadIdx.x;
    int i = blockIdx.x * 256 + t;
    int v = (i < NND) ? g_deg[i] : 0;
    s[t] = v;
    __syncthreads();
#pragma unroll
    for (int off = 1; off < 256; off <<= 1) {
        int x = (t >= off) ? s[t - off] : 0;
        __syncthreads();
        s[t] += x;
        __syncthreads();
    }
    if (i < NND) g_off[i] = s[t] - v;     // exclusive within block
    if (t == 255) g_part[blockIdx.x] = s[255];
}

// pass 2: single-block exclusive scan of block totals (196 blocks <= 256)
__global__ void scan2_k(int nblk) {
    __shared__ int s[256];
    int t = threadIdx.x;
    int v = (t < nblk) ? g_part[t] : 0;
    s[t] = v;
    __syncthreads();
#pragma unroll
    for (int off = 1; off < 256; off <<= 1) {
        int x = (t >= off) ? s[t - off] : 0;
        __syncthreads();
        s[t] += x;
        __syncthreads();
    }
    if (t < nblk) g_part[t] = s[t] - v;
}

// pass 3: add block offsets, init cursors, set sentinel
__global__ void scan3_k() {
    int i = blockIdx.x * blockDim.x + threadIdx.x;
    if (i < NND) {
        int o = g_off[i] + g_part[i >> 8];
        g_off[i] = o;
        g_cur[i] = o;
    }
    if (i == 0) g_off[NND] = EED;
}

__global__ void scatter_k(const int* __restrict__ ei) {
    int e = blockIdx.x * blockDim.x + threadIdx.x;
    if (e >= EED) return;
    int dst = ei[EED + e];
    int pos = atomicAdd(&g_cur[dst], 1);
    g_csr_src[pos] = ei[e];
}

// ---------------- tiled fp32 GEMM, K=128 fixed, 128x128 tile, 8x8/thread ----
__device__ __forceinline__ void gemm_body(const float* __restrict__ A,
                                          const float* __restrict__ B,
                                          const float* __restrict__ bias,
                                          float* __restrict__ Cmat,
                                          int M, int Ncols) {
    __shared__ float sA[16][132];   // padded: softens transpose-store conflicts
    __shared__ float sB[16][128];
    const int tx = threadIdx.x, ty = threadIdx.y;
    const int tid = ty * 16 + tx;
    const int rowBase = blockIdx.y * 128;
    const int colBase = blockIdx.x * 128;
    float acc[8][8] = {};

    for (int kk = 0; kk < 128; kk += 16) {
        // A tile: 128 rows x 16 k = 512 float4; 2 per thread, transposed store
#pragma unroll
        for (int t = 0; t < 2; t++) {
            int idx4 = tid + t * 256;
            int m = idx4 >> 2, kq = idx4 & 3;
            int row = rowBase + m;
            float4 a = (row < M) ? *(const float4*)&A[row * 128 + kk + kq * 4]
                                 : make_float4(0.f, 0.f, 0.f, 0.f);
            sA[kq * 4 + 0][m] = a.x;
            sA[kq * 4 + 1][m] = a.y;
            sA[kq * 4 + 2][m] = a.z;
            sA[kq * 4 + 3][m] = a.w;
        }
        // B tile: 16 k x 128 cols = 512 float4; 2 per thread
#pragma unroll
        for (int t = 0; t < 2; t++) {
            int idx4 = tid + t * 256;
            int k = idx4 >> 5, n4 = idx4 & 31;
            *(float4*)&sB[k][n4 * 4] = *(const float4*)&B[(kk + k) * Ncols + colBase + n4 * 4];
        }
        __syncthreads();
#pragma unroll
        for (int k = 0; k < 16; k++) {
            float4 a0 = *(const float4*)&sA[k][ty * 8];
            float4 a1 = *(const float4*)&sA[k][ty * 8 + 4];
            float4 b0 = *(const float4*)&sB[k][tx * 4];        // cols tx*4..+3
            float4 b1 = *(const float4*)&sB[k][64 + tx * 4];   // cols 64+tx*4..+3
            float ar[8] = {a0.x, a0.y, a0.z, a0.w, a1.x, a1.y, a1.z, a1.w};
            float br[8] = {b0.x, b0.y, b0.z, b0.w, b1.x, b1.y, b1.z, b1.w};
#pragma unroll
            for (int i = 0; i < 8; i++)
#pragma unroll
                for (int j = 0; j < 8; j++)
                    acc[i][j] += ar[i] * br[j];
        }
        __syncthreads();
    }

    int c0 = colBase + tx * 4;
    int c1 = colBase + 64 + tx * 4;
    float4 bia0 = *(const float4*)&bias[c0];
    float4 bia1 = *(const float4*)&bias[c1];
#pragma unroll
    for (int i = 0; i < 8; i++) {
        int row = rowBase + ty * 8 + i;
        if (row < M) {
            float4 o0, o1;
            o0.x = acc[i][0] + bia0.x; o0.y = acc[i][1] + bia0.y;
            o0.z = acc[i][2] + bia0.z; o0.w = acc[i][3] + bia0.w;
            o1.x = acc[i][4] + bia1.x; o1.y = acc[i][5] + bia1.y;
            o1.z = acc[i][6] + bia1.z; o1.w = acc[i][7] + bia1.w;
            *(float4*)&Cmat[row * Ncols + c0] = o0;
            *(float4*)&Cmat[row * Ncols + c1] = o1;
        }
    }
}

__global__ void gemm_qkvs(const float* __restrict__ x_ext, int layer, int use_ext) {
    const float* A = use_ext ? x_ext : g_x;
    gemm_body(A, &g_Wp[layer * DDIM * QKVS], &g_bp[layer * QKVS], g_qkvs, NND, QKVS);
}

__global__ void gemm_out(const float* __restrict__ Wout, const float* __restrict__ bout,
                         float* __restrict__ out) {
    gemm_body(g_x, Wout, bout, out, NND, DDIM);
}

// ---------------- fused attention: warp per dst node, no atomics -------------
// lane layout: h = lane>>2 (head), pl = lane&3; output col block = lane*4
// (note (lane>>2)*16 + (lane&3)*4 == lane*4, so dot-product and output
//  column assignments coincide per lane)
__global__ void attn_fused_k() {
    int gw = (blockIdx.x * blockDim.x + threadIdx.x) >> 5;
    if (gw >= NND) return;
    int lane = threadIdx.x & 31;
    int h = lane >> 2, pl = lane & 3;
    int beg = g_off[gw], end = g_off[gw + 1];

    // ---- pass 1: scores + max ----
    float4 q4 = *(const float4*)&g_qkvs[gw * QKVS + h * CCH + pl * 4];
    float m = -CUDART_INF_F;
    for (int i = beg; i < end; i++) {
        int src = g_csr_src[i];
        float4 k4 = *(const float4*)&g_qkvs[src * QKVS + 128 + h * CCH + pl * 4];
        float s = q4.x * k4.x + q4.y * k4.y + q4.z * k4.z + q4.w * k4.w;
        s += __shfl_xor_sync(0xFFFFFFFFu, s, 1);
        s += __shfl_xor_sync(0xFFFFFFFFu, s, 2);
        s *= 0.25f;                       // 1/sqrt(16)
        if (pl == 0) g_sp[i * 8 + h] = s;
        m = fmaxf(m, s);
    }

    // ---- pass 2: exp, z, and p*v accumulation (registers only) ----
    float z = 0.0f;
    float4 acc = make_float4(0.f, 0.f, 0.f, 0.f);
    for (int i = beg; i < end; i++) {
        int src = g_csr_src[i];
        float p = __expf(g_sp[i * 8 + h] - m);
        z += p;
        float4 v4 = *(const float4*)&g_qkvs[src * QKVS + 256 + lane * 4];
        acc.x += p * v4.x;
        acc.y += p * v4.y;
        acc.z += p * v4.z;
        acc.w += p * v4.w;
    }
    float invz = (beg < end) ? (1.0f / z) : 0.0f;

    // ---- normalize + skip + ReLU ----
    float4 sk = *(const float4*)&g_qkvs[gw * QKVS + 384 + lane * 4];
    float4 o;
    o.x = fmaxf(acc.x * invz + sk.x, 0.f);
    o.y = fmaxf(acc.y * invz + sk.y, 0.f);
    o.z = fmaxf(acc.z * invz + sk.z, 0.f);
    o.w = fmaxf(acc.w * invz + sk.w, 0.f);
    *(float4*)&g_x[gw * DDIM + lane * 4] = o;
}

// ---------------- launch -----------------------------------------------------
extern "C" void kernel_launch(void* const* d_in, const int* in_sizes, int n_in,
                              void* d_out, int out_size) {
    const float* x    = (const float*)d_in[0];
    const int*   ei   = (const int*)d_in[1];
    // d_in[2] = batch (unused: single graph)
    const float* Wq   = (const float*)d_in[3];
    const float* bq   = (const float*)d_in[4];
    const float* Wk   = (const float*)d_in[5];
    const float* bk   = (const float*)d_in[6];
    const float* Wv   = (const float*)d_in[7];
    const float* bv   = (const float*)d_in[8];
    const float* Ws   = (const float*)d_in[9];
    const float* bs   = (const float*)d_in[10];
    const float* Wout = (const float*)d_in[11];
    const float* bout = (const float*)d_in[12];
    float* out = (float*)d_out;

    const int TPB = 256;
    const int nScanBlk = (NND + 255) / 256;            // 196
    const int nEdgeBlk = (EED + TPB - 1) / TPB;
    const int nWarpBlk = (NND + 7) / 8;                // 8 warps/block, warp per node
    dim3 gemmBlk(16, 16);
    dim3 gemmGridQKVS(QKVS / 128, (NND + 127) / 128);  // (4, 391)
    dim3 gemmGridOut(DDIM / 128, (NND + 127) / 128);   // (1, 391)

    // one-time (per launch) prep
    pack_w<<<(LLAY * DDIM * QKVS + TPB - 1) / TPB, TPB>>>(Wq, Wk, Wv, Ws, bq, bk, bv, bs);
    deg_zero_k<<<(NND + TPB - 1) / TPB, TPB>>>();
    hist_k<<<nEdgeBlk, TPB>>>(ei);
    scan1_k<<<nScanBlk, 256>>>();
    scan2_k<<<1, 256>>>(nScanBlk);
    scan3_k<<<(NND + TPB - 1) / TPB, TPB>>>();
    scatter_k<<<nEdgeBlk, TPB>>>(ei);

    for (int l = 0; l < LLAY; l++) {
        gemm_qkvs<<<gemmGridQKVS, gemmBlk>>>(x, l, l == 0 ? 1 : 0);
        attn_fused_k<<<nWarpBlk, TPB>>>();
    }

    gemm_out<<<gemmGridOut, gemmBlk>>>(Wout, bout, out);
}

// round 5
// speedup vs baseline: 1.0625x; 1.0625x over previous
#include <cuda_runtime.h>
#include <math_constants.h>

// Problem constants
#define NND   50000
#define EED   800000
#define DDIM  128
#define HH    8
#define CCH   16
#define LLAY  4
#define QKVS  512   // 4*128 packed output columns: [q|k|v|skip]

typedef unsigned long long u64;

// ---------------- scratch (device globals; no allocation allowed) ----------
__device__ __align__(16) float g_x[NND * DDIM];          // node features between layers
__device__ __align__(16) float g_qkvs[NND * QKVS];       // [q|k|v|skip] per node
__device__ __align__(16) float g_sp[EED * HH];           // per-edge raw scores (CSR order)
__device__ __align__(16) float g_Wp[LLAY * DDIM * QKVS]; // packed weights
__device__ __align__(16) float g_bp[LLAY * QKVS];        // packed biases
// CSR build
__device__ int g_deg[NND];
__device__ int g_off[NND + 1];
__device__ int g_cur[NND];
__device__ int g_part[256];
__device__ int g_csr_src[EED];

// ---------------- weight packing -------------------------------------------
__global__ void pack_w(const float* __restrict__ Wq, const float* __restrict__ Wk,
                       const float* __restrict__ Wv, const float* __restrict__ Ws,
                       const float* __restrict__ bq, const float* __restrict__ bk,
                       const float* __restrict__ bv, const float* __restrict__ bs) {
    int i = blockIdx.x * blockDim.x + threadIdx.x;
    if (i < LLAY * DDIM * QKVS) {
        int l = i >> 16;          // 128*512 = 65536
        int k = (i >> 9) & 127;
        int j = i & 511;
        int which = j >> 7, jj = j & 127;
        const float* W = (which == 0) ? Wq : (which == 1) ? Wk : (which == 2) ? Wv : Ws;
        g_Wp[i] = W[l * (DDIM * DDIM) + k * DDIM + jj];
    }
    if (i < LLAY * QKVS) {
        int l = i >> 9, j = i & 511;
        int which = j >> 7, jj = j & 127;
        const float* b = (which == 0) ? bq : (which == 1) ? bk : (which == 2) ? bv : bs;
        g_bp[i] = b[l * DDIM + jj];
    }
}

// ---------------- CSR build --------------------------------------------------
__global__ void deg_zero_k() {
    int i = blockIdx.x * blockDim.x + threadIdx.x;
    if (i < NND) g_deg[i] = 0;
}

__global__ void hist_k(const int* __restrict__ ei) {
    int e = blockIdx.x * blockDim.x + threadIdx.x;
    if (e < EED) atomicAdd(&g_deg[ei[EED + e]], 1);
}

__global__ void scan1_k() {
    __shared__ int s[256];
    int t = threadIdx.x;
    int i = blockIdx.x * 256 + t;
    int v = (i < NND) ? g_deg[i] : 0;
    s[t] = v;
    __syncthreads();
#pragma unroll
    for (int off = 1; off < 256; off <<= 1) {
        int x = (t >= off) ? s[t - off] : 0;
        __syncthreads();
        s[t] += x;
        __syncthreads();
    }
    if (i < NND) g_off[i] = s[t] - v;     // exclusive within block
    if (t == 255) g_part[blockIdx.x] = s[255];
}

__global__ void scan2_k(int nblk) {
    __shared__ int s[256];
    int t = threadIdx.x;
    int v = (t < nblk) ? g_part[t] : 0;
    s[t] = v;
    __syncthreads();
#pragma unroll
    for (int off = 1; off < 256; off <<= 1) {
        int x = (t >= off) ? s[t - off] : 0;
        __syncthreads();
        s[t] += x;
        __syncthreads();
    }
    if (t < nblk) g_part[t] = s[t] - v;
}

__global__ void scan3_k() {
    int i = blockIdx.x * blockDim.x + threadIdx.x;
    if (i < NND) {
        int o = g_off[i] + g_part[i >> 8];
        g_off[i] = o;
        g_cur[i] = o;
    }
    if (i == 0) g_off[NND] = EED;
}

__global__ void scatter_k(const int* __restrict__ ei) {
    int e = blockIdx.x * blockDim.x + threadIdx.x;
    if (e >= EED) return;
    int dst = ei[EED + e];
    int pos = atomicAdd(&g_cur[dst], 1);
    g_csr_src[pos] = ei[e];
}

// ---------------- tiled fp32 GEMM, K=128 fixed, 128x128 tile, 8x8/thread ----
// Inner product via packed fma.rn.f32x2: 2 IEEE fp32 MACs per instruction.
__device__ __forceinline__ void gemm_body(const float* __restrict__ A,
                                          const float* __restrict__ B,
                                          const float* __restrict__ bias,
                                          float* __restrict__ Cmat,
                                          int M, int Ncols) {
    __shared__ __align__(16) float sA[16][132];   // 528B row stride = 33*16B (aligned)
    __shared__ __align__(16) float sB[16][128];
    const int tx = threadIdx.x, ty = threadIdx.y;
    const int tid = ty * 16 + tx;
    const int rowBase = blockIdx.y * 128;
    const int colBase = blockIdx.x * 128;

    // acc2[i][j] holds C columns (2j, 2j+1) of this thread's pair-block, packed f32x2
    u64 acc2[8][4];
#pragma unroll
    for (int i = 0; i < 8; i++)
#pragma unroll
        for (int j = 0; j < 4; j++) acc2[i][j] = 0ULL;

    for (int kk = 0; kk < 128; kk += 16) {
        // A tile: 128 rows x 16 k = 512 float4; 2 per thread, transposed store
#pragma unroll
        for (int t = 0; t < 2; t++) {
            int idx4 = tid + t * 256;
            int m = idx4 >> 2, kq = idx4 & 3;
            int row = rowBase + m;
            float4 a = (row < M) ? *(const float4*)&A[row * 128 + kk + kq * 4]
                                 : make_float4(0.f, 0.f, 0.f, 0.f);
            sA[kq * 4 + 0][m] = a.x;
            sA[kq * 4 + 1][m] = a.y;
            sA[kq * 4 + 2][m] = a.z;
            sA[kq * 4 + 3][m] = a.w;
        }
        // B tile: 16 k x 128 cols = 512 float4; 2 per thread
#pragma unroll
        for (int t = 0; t < 2; t++) {
            int idx4 = tid + t * 256;
            int k = idx4 >> 5, n4 = idx4 & 31;
            *(float4*)&sB[k][n4 * 4] = *(const float4*)&B[(kk + k) * Ncols + colBase + n4 * 4];
        }
        __syncthreads();
#pragma unroll
        for (int k = 0; k < 16; k++) {
            float4 a0 = *(const float4*)&sA[k][ty * 8];
            float4 a1 = *(const float4*)&sA[k][ty * 8 + 4];
            // b pairs: 16B-aligned 64-bit packed loads straight from smem
            ulonglong2 bp0 = *(const ulonglong2*)&sB[k][tx * 4];        // cols tx*4..+3
            ulonglong2 bp1 = *(const ulonglong2*)&sB[k][64 + tx * 4];   // cols 64+tx*4..+3
            u64 bb[4] = {bp0.x, bp0.y, bp1.x, bp1.y};
            float ar[8] = {a0.x, a0.y, a0.z, a0.w, a1.x, a1.y, a1.z, a1.w};
#pragma unroll
            for (int i = 0; i < 8; i++) {
                u64 a2;
                unsigned int abits = __float_as_uint(ar[i]);
                asm("mov.b64 %0, {%1, %1};" : "=l"(a2) : "r"(abits));
#pragma unroll
                for (int j = 0; j < 4; j++)
                    asm("fma.rn.f32x2 %0, %1, %2, %0;" : "+l"(acc2[i][j]) : "l"(a2), "l"(bb[j]));
            }
        }
        __syncthreads();
    }

    int c0 = colBase + tx * 4;
    int c1 = colBase + 64 + tx * 4;
    float4 bia0 = *(const float4*)&bias[c0];
    float4 bia1 = *(const float4*)&bias[c1];
#pragma unroll
    for (int i = 0; i < 8; i++) {
        int row = rowBase + ty * 8 + i;
        if (row < M) {
            float2 p0 = *(float2*)&acc2[i][0];
            float2 p1 = *(float2*)&acc2[i][1];
            float2 p2 = *(float2*)&acc2[i][2];
            float2 p3 = *(float2*)&acc2[i][3];
            float4 o0, o1;
            o0.x = p0.x + bia0.x; o0.y = p0.y + bia0.y;
            o0.z = p1.x + bia0.z; o0.w = p1.y + bia0.w;
            o1.x = p2.x + bia1.x; o1.y = p2.y + bia1.y;
            o1.z = p3.x + bia1.z; o1.w = p3.y + bia1.w;
            *(float4*)&Cmat[row * Ncols + c0] = o0;
            *(float4*)&Cmat[row * Ncols + c1] = o1;
        }
    }
}

__global__ void gemm_qkvs(const float* __restrict__ x_ext, int layer, int use_ext) {
    const float* A = use_ext ? x_ext : g_x;
    gemm_body(A, &g_Wp[layer * DDIM * QKVS], &g_bp[layer * QKVS], g_qkvs, NND, QKVS);
}

__global__ void gemm_out(const float* __restrict__ Wout, const float* __restrict__ bout,
                         float* __restrict__ out) {
    gemm_body(g_x, Wout, bout, out, NND, DDIM);
}

// ---------------- fused attention: warp per dst node, no atomics -------------
// lane layout: h = lane>>2 (head), pl = lane&3; output col block = lane*4
__global__ void attn_fused_k() {
    int gw = (blockIdx.x * blockDim.x + threadIdx.x) >> 5;
    if (gw >= NND) return;
    int lane = threadIdx.x & 31;
    int h = lane >> 2, pl = lane & 3;
    int beg = g_off[gw], end = g_off[gw + 1];

    // ---- pass 1: scores + max ----
    float4 q4 = *(const float4*)&g_qkvs[gw * QKVS + h * CCH + pl * 4];
    float m = -CUDART_INF_F;
    for (int i = beg; i < end; i++) {
        int src = g_csr_src[i];
        float4 k4 = *(const float4*)&g_qkvs[src * QKVS + 128 + h * CCH + pl * 4];
        float s = q4.x * k4.x + q4.y * k4.y + q4.z * k4.z + q4.w * k4.w;
        s += __shfl_xor_sync(0xFFFFFFFFu, s, 1);
        s += __shfl_xor_sync(0xFFFFFFFFu, s, 2);
        s *= 0.25f;                       // 1/sqrt(16)
        if (pl == 0) g_sp[i * 8 + h] = s;
        m = fmaxf(m, s);
    }

    // ---- pass 2: exp, z, and p*v accumulation (registers only) ----
    float z = 0.0f;
    float4 acc = make_float4(0.f, 0.f, 0.f, 0.f);
    for (int i = beg; i < end; i++) {
        int src = g_csr_src[i];
        float p = __expf(g_sp[i * 8 + h] - m);
        z += p;
        float4 v4 = *(const float4*)&g_qkvs[src * QKVS + 256 + lane * 4];
        acc.x += p * v4.x;
        acc.y += p * v4.y;
        acc.z += p * v4.z;
        acc.w += p * v4.w;
    }
    float invz = (beg < end) ? (1.0f / z) : 0.0f;

    // ---- normalize + skip + ReLU ----
    float4 sk = *(const float4*)&g_qkvs[gw * QKVS + 384 + lane * 4];
    float4 o;
    o.x = fmaxf(acc.x * invz + sk.x, 0.f);
    o.y = fmaxf(acc.y * invz + sk.y, 0.f);
    o.z = fmaxf(acc.z * invz + sk.z, 0.f);
    o.w = fmaxf(acc.w * invz + sk.w, 0.f);
    *(float4*)&g_x[gw * DDIM + lane * 4] = o;
}

// ---------------- launch -----------------------------------------------------
extern "C" void kernel_launch(void* const* d_in, const int* in_sizes, int n_in,
                              void* d_out, int out_size) {
    const float* x    = (const float*)d_in[0];
    const int*   ei   = (const int*)d_in[1];
    // d_in[2] = batch (unused: single graph)
    const float* Wq   = (const float*)d_in[3];
    const float* bq   = (const float*)d_in[4];
    const float* Wk   = (const float*)d_in[5];
    const float* bk   = (const float*)d_in[6];
    const float* Wv   = (const float*)d_in[7];
    const float* bv   = (const float*)d_in[8];
    const float* Ws   = (const float*)d_in[9];
    const float* bs   = (const float*)d_in[10];
    const float* Wout = (const float*)d_in[11];
    const float* bout = (const float*)d_in[12];
    float* out = (float*)d_out;

    const int TPB = 256;
    const int nScanBlk = (NND + 255) / 256;            // 196
    const int nEdgeBlk = (EED + TPB - 1) / TPB;
    const int nWarpBlk = (NND + 7) / 8;                // 8 warps/block, warp per node
    dim3 gemmBlk(16, 16);
    dim3 gemmGridQKVS(QKVS / 128, (NND + 127) / 128);  // (4, 391)
    dim3 gemmGridOut(DDIM / 128, (NND + 127) / 128);   // (1, 391)

    // one-time (per launch) prep
    pack_w<<<(LLAY * DDIM * QKVS + TPB - 1) / TPB, TPB>>>(Wq, Wk, Wv, Ws, bq, bk, bv, bs);
    deg_zero_k<<<(NND + TPB - 1) / TPB, TPB>>>();
    hist_k<<<nEdgeBlk, TPB>>>(ei);
    scan1_k<<<nScanBlk, 256>>>();
    scan2_k<<<1, 256>>>(nScanBlk);
    scan3_k<<<(NND + TPB - 1) / TPB, TPB>>>();
    scatter_k<<<nEdgeBlk, TPB>>>(ei);

    for (int l = 0; l < LLAY; l++) {
        gemm_qkvs<<<gemmGridQKVS, gemmBlk>>>(x, l, l == 0 ? 1 : 0);
        attn_fused_k<<<nWarpBlk, TPB>>>();
    }

    gemm_out<<<gemmGridOut, gemmBlk>>>(Wout, bout, out);
}